// round 16
// baseline (speedup 1.0000x reference)
#include <cuda_runtime.h>
#include <cuda_bf16.h>
#include <cstdint>
#include <cstddef>

// Problem constants (fixed by the dataset)
#define NT 200000
#define NC 100000
#define NI 100000

// ---------------------------------------------------------------------------
// Scratch (device globals; no runtime allocation allowed)
// ---------------------------------------------------------------------------
__device__ float g_agg0[(size_t)NT * 128]; // layer2: card->target sums
__device__ float g_agg2[(size_t)NT * 128]; // layer2: ip->target sums
__device__ float g_agg1[(size_t)NC * 128]; // layer1: target->card sums
__device__ float g_agg3[(size_t)NI * 128]; // layer1: target->ip sums
__device__ float g_h1c[(size_t)NC * 128];  // h1["card"] after lrelu
__device__ float g_h1i[(size_t)NI * 128];  // h1["ip"] after lrelu
__device__ int   g_deg0[NT];
__device__ int   g_deg2[NT];
__device__ int   g_deg1[NC];
__device__ int   g_deg3[NI];
__device__ float g_inv0[NT];
__device__ float g_inv2[NT];
__device__ float g_inv1[NC];
__device__ float g_inv3[NI];
// Pre-transposed, hi/lo-split weights. Slots: 0=w1[1], 1=w1[3], 2=w2[0], 3=w2[2]
// Layout per slot: Wt[n][k] (N-major), bf16.
__device__ __nv_bfloat16 g_wthi[4][128 * 128];
__device__ __nv_bfloat16 g_wtlo[4][128 * 128];

// ---------------------------------------------------------------------------
// Edge aggregation: one warp per edge (unchanged from round 1 — it works).
// ---------------------------------------------------------------------------
__global__ void agg_kernel(const float* __restrict__ x,
                           const int* __restrict__ src,
                           const int* __restrict__ dst,
                           float* __restrict__ agg,
                           int* __restrict__ deg,
                           int E)
{
    int gw   = (int)((blockIdx.x * (unsigned)blockDim.x + threadIdx.x) >> 5);
    int lane = threadIdx.x & 31;
    if (gw >= E) return;
    int s = __ldg(src + gw);
    int d = __ldg(dst + gw);
    float4 v = __ldg(reinterpret_cast<const float4*>(x + (size_t)s * 128) + lane);
    float4* ap = reinterpret_cast<float4*>(agg + (size_t)d * 128) + lane;
    asm volatile("red.global.add.v4.f32 [%0], {%1,%2,%3,%4};"
                 :: "l"(ap), "f"(v.x), "f"(v.y), "f"(v.z), "f"(v.w)
                 : "memory");
    if (lane == 0) atomicAdd(deg + d, 1);
}

__global__ void inv_kernel(const int* __restrict__ deg, float* __restrict__ inv, int n)
{
    int i = blockIdx.x * blockDim.x + threadIdx.x;
    if (i < n) {
        int d = deg[i];
        inv[i] = d > 0 ? 1.0f / (float)d : 0.0f;
    }
}

// ---------------------------------------------------------------------------
// Weight prep: transpose W[k][n] -> Wt[n][k], split into bf16 hi/lo.
// ---------------------------------------------------------------------------
__global__ void wprep_kernel(const float* __restrict__ w1, const float* __restrict__ w2)
{
    int idx = blockIdx.x * blockDim.x + threadIdx.x;
    if (idx >= 4 * 16384) return;
    int slot = idx >> 14;
    int e    = idx & 16383;
    int n    = e >> 7;
    int k    = e & 127;
    const float* W = (slot == 0) ? (w1 + 1 * 16384)
                   : (slot == 1) ? (w1 + 3 * 16384)
                   : (slot == 2) ? (w2 + 0 * 16384)
                                 : (w2 + 2 * 16384);
    float v = __ldg(W + k * 128 + n);
    __nv_bfloat16 hi = __float2bfloat16(v);
    __nv_bfloat16 lo = __float2bfloat16(v - __bfloat162float(hi));
    g_wthi[slot][n * 128 + k] = hi;
    g_wtlo[slot][n * 128 + k] = lo;
}

// ---------------------------------------------------------------------------
// Tensor-core helpers
// ---------------------------------------------------------------------------
__device__ __forceinline__ uint32_t s2u(const void* p)
{
    uint32_t a;
    asm("{ .reg .u64 t; cvta.to.shared.u64 t, %1; cvt.u32.u64 %0, t; }"
        : "=r"(a) : "l"(p));
    return a;
}

__device__ __forceinline__ void ldsm4(uint32_t addr, uint32_t* r)
{
    asm volatile("ldmatrix.sync.aligned.m8n8.x4.shared.b16 {%0,%1,%2,%3}, [%4];"
                 : "=r"(r[0]), "=r"(r[1]), "=r"(r[2]), "=r"(r[3]) : "r"(addr));
}

__device__ __forceinline__ void mma16816(float* c, const uint32_t* a, const uint32_t* b)
{
    asm volatile(
        "mma.sync.aligned.m16n8k16.row.col.f32.bf16.bf16.f32 "
        "{%0,%1,%2,%3}, {%4,%5,%6,%7}, {%8,%9}, {%0,%1,%2,%3};"
        : "+f"(c[0]), "+f"(c[1]), "+f"(c[2]), "+f"(c[3])
        : "r"(a[0]), "r"(a[1]), "r"(a[2]), "r"(a[3]), "r"(b[0]), "r"(b[1]));
}

// ---------------------------------------------------------------------------
// Fused tensor-core GEMM with 3-term bf16 split (fp32-accurate):
//   C = epilogue( sum_{r<R} (A_r * inv_r) @ W_r + [inv_r>0] * b_r )
// BM=BN=128, BK=16 chunks, 256 threads = 8 warps (4x2), warp tile 32x64.
// !FINAL: lrelu epilogue, smem-staged coalesced fp32 [M,128] write.
// FINAL (R=2): fused w_out projection + softmax, writes [M,2] to d_out.
// ---------------------------------------------------------------------------
#define AS 24  // padded smem row stride in halves (48B) — conflict-free ldmatrix

template <int R, bool LRELU, bool FINAL>
__global__ void __launch_bounds__(256)
gemm_tc(const float* __restrict__ A0, const float* __restrict__ inv0,
        const float* __restrict__ A1, const float* __restrict__ inv1,
        const __nv_bfloat16* __restrict__ Wthi0, const __nv_bfloat16* __restrict__ Wtlo0,
        const __nv_bfloat16* __restrict__ Wthi1, const __nv_bfloat16* __restrict__ Wtlo1,
        const float* __restrict__ bias0, const float* __restrict__ bias1,
        const float* __restrict__ wout, const float* __restrict__ bout,
        float* __restrict__ C, int M)
{
    extern __shared__ __align__(16) char smbuf[];
    __nv_bfloat16* sAhi = reinterpret_cast<__nv_bfloat16*>(smbuf);
    __nv_bfloat16* sAlo = sAhi + 128 * AS;
    __nv_bfloat16* sWhi = sAlo + 128 * AS;
    __nv_bfloat16* sWlo = sWhi + 128 * AS;
    float* stage = reinterpret_cast<float*>(sWlo + 128 * AS); // [128][132] (!FINAL)
    float* slog  = reinterpret_cast<float*>(sWlo + 128 * AS); // [128][2]   (FINAL)

    const int tid  = threadIdx.x;
    const int lane = tid & 31;
    const int warp = tid >> 5;
    const int wm   = warp >> 1;   // 0..3
    const int wn   = warp & 1;    // 0..1
    const int rowBase = blockIdx.x * 128;

    if (FINAL && tid < 256) slog[tid] = 0.0f;

    float acc[2][8][4];
#pragma unroll
    for (int i = 0; i < 2; ++i)
#pragma unroll
        for (int j = 0; j < 8; ++j)
#pragma unroll
            for (int q = 0; q < 4; ++q) acc[i][j][q] = 0.0f;

    // tile-load thread mapping: each thread handles 8 contiguous elements
    const int r_ = tid >> 1;          // row 0..127 (A row & W n-row)
    const int h_ = (tid & 1) * 8;     // 0 or 8 within the 16-wide K chunk

#pragma unroll 1
    for (int s = 0; s < R * 8; ++s) {
        const int rel = s >> 3;
        const int kk0 = (s & 7) * 16;
        const float* Ap   = (R == 2 && rel) ? A1   : A0;
        const float* invp = (R == 2 && rel) ? inv1 : inv0;
        const __nv_bfloat16* whp = (R == 2 && rel) ? Wthi1 : Wthi0;
        const __nv_bfloat16* wlp = (R == 2 && rel) ? Wtlo1 : Wtlo0;

        // ---- load + split A (fp32 -> bf16 hi/lo, scaled by 1/deg) ----
        {
            float f[8];
            const int gr = rowBase + r_;
            if (gr < M) {
                const float4* ap = reinterpret_cast<const float4*>(Ap + (size_t)gr * 128 + kk0 + h_);
                float4 va = __ldg(ap);
                float4 vb = __ldg(ap + 1);
                float iv = __ldg(invp + gr);
                f[0] = va.x * iv; f[1] = va.y * iv; f[2] = va.z * iv; f[3] = va.w * iv;
                f[4] = vb.x * iv; f[5] = vb.y * iv; f[6] = vb.z * iv; f[7] = vb.w * iv;
            } else {
#pragma unroll
                for (int j = 0; j < 8; ++j) f[j] = 0.0f;
            }
            uint4 uh, ul;
            uint32_t* ph = &uh.x;
            uint32_t* pl = &ul.x;
#pragma unroll
            for (int j = 0; j < 4; ++j) {
                float2 f2 = make_float2(f[2 * j], f[2 * j + 1]);
                __nv_bfloat162 h2 = __float22bfloat162_rn(f2);
                float2 hb = __bfloat1622float2(h2);
                __nv_bfloat162 l2 = __float22bfloat162_rn(make_float2(f2.x - hb.x, f2.y - hb.y));
                ph[j] = *reinterpret_cast<uint32_t*>(&h2);
                pl[j] = *reinterpret_cast<uint32_t*>(&l2);
            }
            *reinterpret_cast<uint4*>(sAhi + r_ * AS + h_) = uh;
            *reinterpret_cast<uint4*>(sAlo + r_ * AS + h_) = ul;
        }
        // ---- load W tiles (already bf16 hi/lo, Wt[n][k]) ----
        {
            const uint4* gh = reinterpret_cast<const uint4*>(whp + r_ * 128 + kk0 + h_);
            const uint4* gl = reinterpret_cast<const uint4*>(wlp + r_ * 128 + kk0 + h_);
            *reinterpret_cast<uint4*>(sWhi + r_ * AS + h_) = __ldg(gh);
            *reinterpret_cast<uint4*>(sWlo + r_ * AS + h_) = __ldg(gl);
        }
        __syncthreads();

        // ---- compute ----
        uint32_t ahi[2][4], alo[2][4];
#pragma unroll
        for (int mf = 0; mf < 2; ++mf) {
            int rrow = wm * 32 + mf * 16 + (lane & 15);
            int kc   = (lane >> 4) * 8;
            ldsm4(s2u(sAhi + rrow * AS + kc), ahi[mf]);
            ldsm4(s2u(sAlo + rrow * AS + kc), alo[mf]);
        }
#pragma unroll
        for (int np = 0; np < 4; ++np) {
            int n0   = wn * 64 + np * 16;
            int brow = n0 + (lane & 7) + ((lane >> 4) & 1) * 8;
            int bkc  = ((lane >> 3) & 1) * 8;
            uint32_t bhi[4], blo[4];
            ldsm4(s2u(sWhi + brow * AS + bkc), bhi);
            ldsm4(s2u(sWlo + brow * AS + bkc), blo);
#pragma unroll
            for (int mf = 0; mf < 2; ++mf) {
#pragma unroll
                for (int nn = 0; nn < 2; ++nn) {
                    float* c = acc[mf][np * 2 + nn];
                    mma16816(c, ahi[mf], bhi + nn * 2);
                    mma16816(c, ahi[mf], blo + nn * 2);
                    mma16816(c, alo[mf], bhi + nn * 2);
                }
            }
        }
        __syncthreads();
    }

    // -----------------------------------------------------------------------
    // Epilogue
    // -----------------------------------------------------------------------
    const int g = lane >> 2;
    const int t = lane & 3;

    if (FINAL) {
        // per-warp bias.wout scalars over this warp's 64 columns
        float s00 = 0.f, s01 = 0.f, s10 = 0.f, s11 = 0.f;
        {
            int cA = wn * 64 + lane;
            int cB = cA + 32;
            float b0A = __ldg(bias0 + cA), b0B = __ldg(bias0 + cB);
            float b1A = __ldg(bias1 + cA), b1B = __ldg(bias1 + cB);
            float wA0 = __ldg(wout + cA * 2), wA1 = __ldg(wout + cA * 2 + 1);
            float wB0 = __ldg(wout + cB * 2), wB1 = __ldg(wout + cB * 2 + 1);
            s00 = b0A * wA0 + b0B * wB0;
            s01 = b0A * wA1 + b0B * wB1;
            s10 = b1A * wA0 + b1B * wB0;
            s11 = b1A * wA1 + b1B * wB1;
#pragma unroll
            for (int off = 16; off; off >>= 1) {
                s00 += __shfl_xor_sync(0xffffffffu, s00, off);
                s01 += __shfl_xor_sync(0xffffffffu, s01, off);
                s10 += __shfl_xor_sync(0xffffffffu, s10, off);
                s11 += __shfl_xor_sync(0xffffffffu, s11, off);
            }
        }
        float p[2][2][2];
#pragma unroll
        for (int i = 0; i < 2; ++i)
#pragma unroll
            for (int j = 0; j < 2; ++j) { p[i][j][0] = 0.f; p[i][j][1] = 0.f; }
#pragma unroll
        for (int nf = 0; nf < 8; ++nf) {
            int col0 = wn * 64 + nf * 8 + t * 2;
            float4 w4 = __ldg(reinterpret_cast<const float4*>(wout + col0 * 2));
            // w4 = {wout[c0][0], wout[c0][1], wout[c0+1][0], wout[c0+1][1]}
#pragma unroll
            for (int mf = 0; mf < 2; ++mf) {
                const float* c = acc[mf][nf];
                p[mf][0][0] += c[0] * w4.x + c[1] * w4.z;
                p[mf][0][1] += c[0] * w4.y + c[1] * w4.w;
                p[mf][1][0] += c[2] * w4.x + c[3] * w4.z;
                p[mf][1][1] += c[2] * w4.y + c[3] * w4.w;
            }
        }
#pragma unroll
        for (int off = 1; off <= 2; off <<= 1) {
#pragma unroll
            for (int mf = 0; mf < 2; ++mf)
#pragma unroll
                for (int rh = 0; rh < 2; ++rh) {
                    p[mf][rh][0] += __shfl_xor_sync(0xffffffffu, p[mf][rh][0], off);
                    p[mf][rh][1] += __shfl_xor_sync(0xffffffffu, p[mf][rh][1], off);
                }
        }
        if (t == 0) {
#pragma unroll
            for (int mf = 0; mf < 2; ++mf)
#pragma unroll
                for (int rh = 0; rh < 2; ++rh) {
                    int rloc = wm * 32 + mf * 16 + g + rh * 8;
                    int gr   = rowBase + rloc;
                    float m0 = 0.f, m1 = 0.f;
                    if (gr < M) {
                        m0 = (__ldg(inv0 + gr) > 0.f) ? 1.f : 0.f;
                        m1 = (__ldg(inv1 + gr) > 0.f) ? 1.f : 0.f;
                    }
                    atomicAdd(&slog[rloc * 2 + 0], p[mf][rh][0] + m0 * s00 + m1 * s10);
                    atomicAdd(&slog[rloc * 2 + 1], p[mf][rh][1] + m0 * s01 + m1 * s11);
                }
        }
        __syncthreads();
        if (tid < 128) {
            int gr = rowBase + tid;
            if (gr < M) {
                float l0 = slog[tid * 2 + 0] + __ldg(bout + 0);
                float l1 = slog[tid * 2 + 1] + __ldg(bout + 1);
                float mx = fmaxf(l0, l1);
                float e0 = expf(l0 - mx);
                float e1 = expf(l1 - mx);
                float si = 1.0f / (e0 + e1);
                C[(size_t)gr * 2 + 0] = e0 * si;
                C[(size_t)gr * 2 + 1] = e1 * si;
            }
        }
    } else {
        // bias + mask + lrelu, stage to smem for coalesced write
#pragma unroll
        for (int mf = 0; mf < 2; ++mf) {
            int r0loc = wm * 32 + mf * 16 + g;
            int gr0 = rowBase + r0loc;
            int gr1 = gr0 + 8;
            float m0 = (gr0 < M && __ldg(inv0 + gr0) > 0.f) ? 1.f : 0.f;
            float m1 = (gr1 < M && __ldg(inv0 + gr1) > 0.f) ? 1.f : 0.f;
#pragma unroll
            for (int nf = 0; nf < 8; ++nf) {
                int col = wn * 64 + nf * 8 + t * 2;
                float bva = __ldg(bias0 + col);
                float bvb = __ldg(bias0 + col + 1);
                const float* c = acc[mf][nf];
                float v0 = c[0] + m0 * bva;
                float v1 = c[1] + m0 * bvb;
                float v2 = c[2] + m1 * bva;
                float v3 = c[3] + m1 * bvb;
                if (LRELU) {
                    v0 = v0 > 0.f ? v0 : 0.01f * v0;
                    v1 = v1 > 0.f ? v1 : 0.01f * v1;
                    v2 = v2 > 0.f ? v2 : 0.01f * v2;
                    v3 = v3 > 0.f ? v3 : 0.01f * v3;
                }
                stage[r0loc * 132 + col]       = v0;
                stage[r0loc * 132 + col + 1]   = v1;
                stage[(r0loc + 8) * 132 + col]     = v2;
                stage[(r0loc + 8) * 132 + col + 1] = v3;
            }
        }
        __syncthreads();
#pragma unroll 4
        for (int it = 0; it < 16; ++it) {
            int row = it * 8 + (tid >> 5);
            int c4  = (tid & 31) * 4;
            int gr  = rowBase + row;
            if (gr < M) {
                float4 v = *reinterpret_cast<const float4*>(stage + row * 132 + c4);
                *reinterpret_cast<float4*>(C + (size_t)gr * 128 + c4) = v;
            }
        }
    }
}

// ---------------------------------------------------------------------------
// Host launcher
// ---------------------------------------------------------------------------
static const int SMEM_TILES = 4 * 128 * AS * 2;              // 24576 B
static const int SMEM_L1    = SMEM_TILES + 128 * 132 * 4;    // 92160 B
static const int SMEM_FIN   = SMEM_TILES + 256 * 4;          // 25600 B

extern "C" void kernel_launch(void* const* d_in, const int* in_sizes, int n_in,
                              void* d_out, int out_size)
{
    const float* x_target = (const float*)d_in[0];
    const float* w1    = (const float*)d_in[3];
    const float* b1    = (const float*)d_in[4];
    const float* w2    = (const float*)d_in[5];
    const float* b2    = (const float*)d_in[6];
    const float* w_out = (const float*)d_in[7];
    const float* b_out = (const float*)d_in[8];
    const int* src0 = (const int*)d_in[9];
    const int* dst0 = (const int*)d_in[10];
    const int* src1 = (const int*)d_in[11];
    const int* dst1 = (const int*)d_in[12];
    const int* src2 = (const int*)d_in[13];
    const int* dst2 = (const int*)d_in[14];
    const int* src3 = (const int*)d_in[15];
    const int* dst3 = (const int*)d_in[16];
    const int E0 = in_sizes[9];
    const int E1 = in_sizes[11];
    const int E2 = in_sizes[13];
    const int E3 = in_sizes[15];

    float *agg0, *agg1, *agg2, *agg3, *h1c, *h1i;
    float *inv0, *inv1, *inv2, *inv3;
    int *deg0, *deg1, *deg2, *deg3;
    __nv_bfloat16 *wthi, *wtlo;
    cudaGetSymbolAddress((void**)&agg0, g_agg0);
    cudaGetSymbolAddress((void**)&agg1, g_agg1);
    cudaGetSymbolAddress((void**)&agg2, g_agg2);
    cudaGetSymbolAddress((void**)&agg3, g_agg3);
    cudaGetSymbolAddress((void**)&h1c,  g_h1c);
    cudaGetSymbolAddress((void**)&h1i,  g_h1i);
    cudaGetSymbolAddress((void**)&deg0, g_deg0);
    cudaGetSymbolAddress((void**)&deg1, g_deg1);
    cudaGetSymbolAddress((void**)&deg2, g_deg2);
    cudaGetSymbolAddress((void**)&deg3, g_deg3);
    cudaGetSymbolAddress((void**)&inv0, g_inv0);
    cudaGetSymbolAddress((void**)&inv1, g_inv1);
    cudaGetSymbolAddress((void**)&inv2, g_inv2);
    cudaGetSymbolAddress((void**)&inv3, g_inv3);
    cudaGetSymbolAddress((void**)&wthi, g_wthi);
    cudaGetSymbolAddress((void**)&wtlo, g_wtlo);

    // allow >48KB dynamic smem on the layer-1 GEMM (idempotent)
    cudaFuncSetAttribute(gemm_tc<1, true, false>,
                         cudaFuncAttributeMaxDynamicSharedMemorySize, SMEM_L1);

    // Zero accumulators
    cudaMemsetAsync(agg0, 0, (size_t)NT * 128 * sizeof(float));
    cudaMemsetAsync(agg2, 0, (size_t)NT * 128 * sizeof(float));
    cudaMemsetAsync(agg1, 0, (size_t)NC * 128 * sizeof(float));
    cudaMemsetAsync(agg3, 0, (size_t)NI * 128 * sizeof(float));
    cudaMemsetAsync(deg0, 0, (size_t)NT * sizeof(int));
    cudaMemsetAsync(deg2, 0, (size_t)NT * sizeof(int));
    cudaMemsetAsync(deg1, 0, (size_t)NC * sizeof(int));
    cudaMemsetAsync(deg3, 0, (size_t)NI * sizeof(int));

    // Weight prep (transpose + hi/lo split)
    wprep_kernel<<<(4 * 16384 + 255) / 256, 256>>>(w1, w2);

    // ---- Layer 1 (only dst types card & ip are live) ----
    agg_kernel<<<(E1 + 7) / 8, 256>>>(x_target, src1, dst1, agg1, deg1, E1);
    agg_kernel<<<(E3 + 7) / 8, 256>>>(x_target, src3, dst3, agg3, deg3, E3);
    inv_kernel<<<(NC + 255) / 256, 256>>>(deg1, inv1, NC);
    inv_kernel<<<(NI + 255) / 256, 256>>>(deg3, inv3, NI);

    gemm_tc<1, true, false><<<(NC + 127) / 128, 256, SMEM_L1>>>(
        agg1, inv1, nullptr, nullptr,
        wthi + 0 * 16384, wtlo + 0 * 16384, nullptr, nullptr,
        b1 + 128, nullptr, nullptr, nullptr, h1c, NC);
    gemm_tc<1, true, false><<<(NI + 127) / 128, 256, SMEM_L1>>>(
        agg3, inv3, nullptr, nullptr,
        wthi + 1 * 16384, wtlo + 1 * 16384, nullptr, nullptr,
        b1 + 384, nullptr, nullptr, nullptr, h1i, NI);

    // ---- Layer 2 (only dst type target is live) ----
    agg_kernel<<<(E0 + 7) / 8, 256>>>(h1c, src0, dst0, agg0, deg0, E0);
    agg_kernel<<<(E2 + 7) / 8, 256>>>(h1i, src2, dst2, agg2, deg2, E2);
    inv_kernel<<<(NT + 255) / 256, 256>>>(deg0, inv0, NT);
    inv_kernel<<<(NT + 255) / 256, 256>>>(deg2, inv2, NT);

    gemm_tc<2, false, true><<<(NT + 127) / 128, 256, SMEM_FIN>>>(
        agg0, inv0, agg2, inv2,
        wthi + 2 * 16384, wtlo + 2 * 16384, wthi + 3 * 16384, wtlo + 3 * 16384,
        b2 + 0, b2 + 256, w_out, b_out, (float*)d_out, NT);
}

// round 17
// speedup vs baseline: 1.0036x; 1.0036x over previous
#include <cuda_runtime.h>
#include <cuda_bf16.h>
#include <cstdint>
#include <cstddef>

// Problem constants (fixed by the dataset)
#define NT 200000
#define NC 100000
#define NI 100000

// ---------------------------------------------------------------------------
// Scratch (device globals; no runtime allocation allowed)
// ---------------------------------------------------------------------------
__device__ float g_agg0[(size_t)NT * 128]; // layer2: card->target sums
__device__ float g_agg2[(size_t)NT * 128]; // layer2: ip->target sums
__device__ float g_agg1[(size_t)NC * 128]; // layer1: target->card sums
__device__ float g_agg3[(size_t)NI * 128]; // layer1: target->ip sums
__device__ float g_h1c[(size_t)NC * 128];  // h1["card"] after lrelu
__device__ float g_h1i[(size_t)NI * 128];  // h1["ip"] after lrelu
__device__ int   g_deg0[NT];
__device__ int   g_deg2[NT];
__device__ int   g_deg1[NC];
__device__ int   g_deg3[NI];
__device__ float g_inv0[NT];
__device__ float g_inv2[NT];
__device__ float g_inv1[NC];
__device__ float g_inv3[NI];
// Pre-transposed, hi/lo-split weights. Slots: 0=w1[1], 1=w1[3], 2=w2[0], 3=w2[2]
// Layout per slot: Wt[n][k] (N-major), bf16.
__device__ __nv_bfloat16 g_wthi[4][128 * 128];
__device__ __nv_bfloat16 g_wtlo[4][128 * 128];

// ---------------------------------------------------------------------------
// Edge aggregation: one warp per edge (unchanged from round 1 — it works).
// ---------------------------------------------------------------------------
__global__ void agg_kernel(const float* __restrict__ x,
                           const int* __restrict__ src,
                           const int* __restrict__ dst,
                           float* __restrict__ agg,
                           int* __restrict__ deg,
                           int E)
{
    int gw   = (int)((blockIdx.x * (unsigned)blockDim.x + threadIdx.x) >> 5);
    int lane = threadIdx.x & 31;
    if (gw >= E) return;
    int s = __ldg(src + gw);
    int d = __ldg(dst + gw);
    float4 v = __ldg(reinterpret_cast<const float4*>(x + (size_t)s * 128) + lane);
    float4* ap = reinterpret_cast<float4*>(agg + (size_t)d * 128) + lane;
    asm volatile("red.global.add.v4.f32 [%0], {%1,%2,%3,%4};"
                 :: "l"(ap), "f"(v.x), "f"(v.y), "f"(v.z), "f"(v.w)
                 : "memory");
    if (lane == 0) atomicAdd(deg + d, 1);
}

__global__ void inv_kernel(const int* __restrict__ deg, float* __restrict__ inv, int n)
{
    int i = blockIdx.x * blockDim.x + threadIdx.x;
    if (i < n) {
        int d = deg[i];
        inv[i] = d > 0 ? 1.0f / (float)d : 0.0f;
    }
}

// ---------------------------------------------------------------------------
// Weight prep: transpose W[k][n] -> Wt[n][k], split into bf16 hi/lo.
// ---------------------------------------------------------------------------
__global__ void wprep_kernel(const float* __restrict__ w1, const float* __restrict__ w2)
{
    int idx = blockIdx.x * blockDim.x + threadIdx.x;
    if (idx >= 4 * 16384) return;
    int slot = idx >> 14;
    int e    = idx & 16383;
    int n    = e >> 7;
    int k    = e & 127;
    const float* W = (slot == 0) ? (w1 + 1 * 16384)
                   : (slot == 1) ? (w1 + 3 * 16384)
                   : (slot == 2) ? (w2 + 0 * 16384)
                                 : (w2 + 2 * 16384);
    float v = __ldg(W + k * 128 + n);
    __nv_bfloat16 hi = __float2bfloat16(v);
    __nv_bfloat16 lo = __float2bfloat16(v - __bfloat162float(hi));
    g_wthi[slot][n * 128 + k] = hi;
    g_wtlo[slot][n * 128 + k] = lo;
}

// ---------------------------------------------------------------------------
// Tensor-core helpers
// ---------------------------------------------------------------------------
__device__ __forceinline__ uint32_t s2u(const void* p)
{
    uint32_t a;
    asm("{ .reg .u64 t; cvta.to.shared.u64 t, %1; cvt.u32.u64 %0, t; }"
        : "=r"(a) : "l"(p));
    return a;
}

__device__ __forceinline__ void ldsm4(uint32_t addr, uint32_t* r)
{
    asm volatile("ldmatrix.sync.aligned.m8n8.x4.shared.b16 {%0,%1,%2,%3}, [%4];"
                 : "=r"(r[0]), "=r"(r[1]), "=r"(r[2]), "=r"(r[3]) : "r"(addr));
}

__device__ __forceinline__ void mma16816(float* c, const uint32_t* a, const uint32_t* b)
{
    asm volatile(
        "mma.sync.aligned.m16n8k16.row.col.f32.bf16.bf16.f32 "
        "{%0,%1,%2,%3}, {%4,%5,%6,%7}, {%8,%9}, {%0,%1,%2,%3};"
        : "+f"(c[0]), "+f"(c[1]), "+f"(c[2]), "+f"(c[3])
        : "r"(a[0]), "r"(a[1]), "r"(a[2]), "r"(a[3]), "r"(b[0]), "r"(b[1]));
}

// ---------------------------------------------------------------------------
// Fused tensor-core GEMM with 3-term bf16 split (fp32-accurate):
//   C = epilogue( sum_{r<R} (A_r * inv_r) @ W_r + [inv_r>0] * b_r )
// BM=BN=128, BK=16 chunks, 256 threads = 8 warps (4x2), warp tile 32x64.
// !FINAL: lrelu epilogue, smem-staged coalesced fp32 [M,128] write.
// FINAL (R=2): fused w_out projection + softmax, writes [M,2] to d_out.
// ---------------------------------------------------------------------------
#define AS 24  // padded smem row stride in halves (48B) — conflict-free ldmatrix

template <int R, bool LRELU, bool FINAL>
__global__ void __launch_bounds__(256)
gemm_tc(const float* __restrict__ A0, const float* __restrict__ inv0,
        const float* __restrict__ A1, const float* __restrict__ inv1,
        const __nv_bfloat16* __restrict__ Wthi0, const __nv_bfloat16* __restrict__ Wtlo0,
        const __nv_bfloat16* __restrict__ Wthi1, const __nv_bfloat16* __restrict__ Wtlo1,
        const float* __restrict__ bias0, const float* __restrict__ bias1,
        const float* __restrict__ wout, const float* __restrict__ bout,
        float* __restrict__ C, int M)
{
    extern __shared__ __align__(16) char smbuf[];
    __nv_bfloat16* sAhi = reinterpret_cast<__nv_bfloat16*>(smbuf);
    __nv_bfloat16* sAlo = sAhi + 128 * AS;
    __nv_bfloat16* sWhi = sAlo + 128 * AS;
    __nv_bfloat16* sWlo = sWhi + 128 * AS;
    float* stage = reinterpret_cast<float*>(sWlo + 128 * AS); // [128][132] (!FINAL)
    float* slog  = reinterpret_cast<float*>(sWlo + 128 * AS); // [128][2]   (FINAL)

    const int tid  = threadIdx.x;
    const int lane = tid & 31;
    const int warp = tid >> 5;
    const int wm   = warp >> 1;   // 0..3
    const int wn   = warp & 1;    // 0..1
    const int rowBase = blockIdx.x * 128;

    if (FINAL && tid < 256) slog[tid] = 0.0f;

    float acc[2][8][4];
#pragma unroll
    for (int i = 0; i < 2; ++i)
#pragma unroll
        for (int j = 0; j < 8; ++j)
#pragma unroll
            for (int q = 0; q < 4; ++q) acc[i][j][q] = 0.0f;

    // tile-load thread mapping: each thread handles 8 contiguous elements
    const int r_ = tid >> 1;          // row 0..127 (A row & W n-row)
    const int h_ = (tid & 1) * 8;     // 0 or 8 within the 16-wide K chunk

#pragma unroll 1
    for (int s = 0; s < R * 8; ++s) {
        const int rel = s >> 3;
        const int kk0 = (s & 7) * 16;
        const float* Ap   = (R == 2 && rel) ? A1   : A0;
        const float* invp = (R == 2 && rel) ? inv1 : inv0;
        const __nv_bfloat16* whp = (R == 2 && rel) ? Wthi1 : Wthi0;
        const __nv_bfloat16* wlp = (R == 2 && rel) ? Wtlo1 : Wtlo0;

        // ---- load + split A (fp32 -> bf16 hi/lo, scaled by 1/deg) ----
        {
            float f[8];
            const int gr = rowBase + r_;
            if (gr < M) {
                const float4* ap = reinterpret_cast<const float4*>(Ap + (size_t)gr * 128 + kk0 + h_);
                float4 va = __ldg(ap);
                float4 vb = __ldg(ap + 1);
                float iv = __ldg(invp + gr);
                f[0] = va.x * iv; f[1] = va.y * iv; f[2] = va.z * iv; f[3] = va.w * iv;
                f[4] = vb.x * iv; f[5] = vb.y * iv; f[6] = vb.z * iv; f[7] = vb.w * iv;
            } else {
#pragma unroll
                for (int j = 0; j < 8; ++j) f[j] = 0.0f;
            }
            uint4 uh, ul;
            uint32_t* ph = &uh.x;
            uint32_t* pl = &ul.x;
#pragma unroll
            for (int j = 0; j < 4; ++j) {
                float2 f2 = make_float2(f[2 * j], f[2 * j + 1]);
                __nv_bfloat162 h2 = __float22bfloat162_rn(f2);
                float2 hb = __bfloat1622float2(h2);
                __nv_bfloat162 l2 = __float22bfloat162_rn(make_float2(f2.x - hb.x, f2.y - hb.y));
                ph[j] = *reinterpret_cast<uint32_t*>(&h2);
                pl[j] = *reinterpret_cast<uint32_t*>(&l2);
            }
            *reinterpret_cast<uint4*>(sAhi + r_ * AS + h_) = uh;
            *reinterpret_cast<uint4*>(sAlo + r_ * AS + h_) = ul;
        }
        // ---- load W tiles (already bf16 hi/lo, Wt[n][k]) ----
        {
            const uint4* gh = reinterpret_cast<const uint4*>(whp + r_ * 128 + kk0 + h_);
            const uint4* gl = reinterpret_cast<const uint4*>(wlp + r_ * 128 + kk0 + h_);
            *reinterpret_cast<uint4*>(sWhi + r_ * AS + h_) = __ldg(gh);
            *reinterpret_cast<uint4*>(sWlo + r_ * AS + h_) = __ldg(gl);
        }
        __syncthreads();

        // ---- compute ----
        uint32_t ahi[2][4], alo[2][4];
#pragma unroll
        for (int mf = 0; mf < 2; ++mf) {
            int rrow = wm * 32 + mf * 16 + (lane & 15);
            int kc   = (lane >> 4) * 8;
            ldsm4(s2u(sAhi + rrow * AS + kc), ahi[mf]);
            ldsm4(s2u(sAlo + rrow * AS + kc), alo[mf]);
        }
#pragma unroll
        for (int np = 0; np < 4; ++np) {
            int n0   = wn * 64 + np * 16;
            int brow = n0 + (lane & 7) + ((lane >> 4) & 1) * 8;
            int bkc  = ((lane >> 3) & 1) * 8;
            uint32_t bhi[4], blo[4];
            ldsm4(s2u(sWhi + brow * AS + bkc), bhi);
            ldsm4(s2u(sWlo + brow * AS + bkc), blo);
#pragma unroll
            for (int mf = 0; mf < 2; ++mf) {
#pragma unroll
                for (int nn = 0; nn < 2; ++nn) {
                    float* c = acc[mf][np * 2 + nn];
                    mma16816(c, ahi[mf], bhi + nn * 2);
                    mma16816(c, ahi[mf], blo + nn * 2);
                    mma16816(c, alo[mf], bhi + nn * 2);
                }
            }
        }
        __syncthreads();
    }

    // -----------------------------------------------------------------------
    // Epilogue
    // -----------------------------------------------------------------------
    const int g = lane >> 2;
    const int t = lane & 3;

    if (FINAL) {
        // per-warp bias.wout scalars over this warp's 64 columns
        float s00 = 0.f, s01 = 0.f, s10 = 0.f, s11 = 0.f;
        {
            int cA = wn * 64 + lane;
            int cB = cA + 32;
            float b0A = __ldg(bias0 + cA), b0B = __ldg(bias0 + cB);
            float b1A = __ldg(bias1 + cA), b1B = __ldg(bias1 + cB);
            float wA0 = __ldg(wout + cA * 2), wA1 = __ldg(wout + cA * 2 + 1);
            float wB0 = __ldg(wout + cB * 2), wB1 = __ldg(wout + cB * 2 + 1);
            s00 = b0A * wA0 + b0B * wB0;
            s01 = b0A * wA1 + b0B * wB1;
            s10 = b1A * wA0 + b1B * wB0;
            s11 = b1A * wA1 + b1B * wB1;
#pragma unroll
            for (int off = 16; off; off >>= 1) {
                s00 += __shfl_xor_sync(0xffffffffu, s00, off);
                s01 += __shfl_xor_sync(0xffffffffu, s01, off);
                s10 += __shfl_xor_sync(0xffffffffu, s10, off);
                s11 += __shfl_xor_sync(0xffffffffu, s11, off);
            }
        }
        float p[2][2][2];
#pragma unroll
        for (int i = 0; i < 2; ++i)
#pragma unroll
            for (int j = 0; j < 2; ++j) { p[i][j][0] = 0.f; p[i][j][1] = 0.f; }
#pragma unroll
        for (int nf = 0; nf < 8; ++nf) {
            int col0 = wn * 64 + nf * 8 + t * 2;
            float4 w4 = __ldg(reinterpret_cast<const float4*>(wout + col0 * 2));
            // w4 = {wout[c0][0], wout[c0][1], wout[c0+1][0], wout[c0+1][1]}
#pragma unroll
            for (int mf = 0; mf < 2; ++mf) {
                const float* c = acc[mf][nf];
                p[mf][0][0] += c[0] * w4.x + c[1] * w4.z;
                p[mf][0][1] += c[0] * w4.y + c[1] * w4.w;
                p[mf][1][0] += c[2] * w4.x + c[3] * w4.z;
                p[mf][1][1] += c[2] * w4.y + c[3] * w4.w;
            }
        }
#pragma unroll
        for (int off = 1; off <= 2; off <<= 1) {
#pragma unroll
            for (int mf = 0; mf < 2; ++mf)
#pragma unroll
                for (int rh = 0; rh < 2; ++rh) {
                    p[mf][rh][0] += __shfl_xor_sync(0xffffffffu, p[mf][rh][0], off);
                    p[mf][rh][1] += __shfl_xor_sync(0xffffffffu, p[mf][rh][1], off);
                }
        }
        if (t == 0) {
#pragma unroll
            for (int mf = 0; mf < 2; ++mf)
#pragma unroll
                for (int rh = 0; rh < 2; ++rh) {
                    int rloc = wm * 32 + mf * 16 + g + rh * 8;
                    int gr   = rowBase + rloc;
                    float m0 = 0.f, m1 = 0.f;
                    if (gr < M) {
                        m0 = (__ldg(inv0 + gr) > 0.f) ? 1.f : 0.f;
                        m1 = (__ldg(inv1 + gr) > 0.f) ? 1.f : 0.f;
                    }
                    atomicAdd(&slog[rloc * 2 + 0], p[mf][rh][0] + m0 * s00 + m1 * s10);
                    atomicAdd(&slog[rloc * 2 + 1], p[mf][rh][1] + m0 * s01 + m1 * s11);
                }
        }
        __syncthreads();
        if (tid < 128) {
            int gr = rowBase + tid;
            if (gr < M) {
                float l0 = slog[tid * 2 + 0] + __ldg(bout + 0);
                float l1 = slog[tid * 2 + 1] + __ldg(bout + 1);
                float mx = fmaxf(l0, l1);
                float e0 = expf(l0 - mx);
                float e1 = expf(l1 - mx);
                float si = 1.0f / (e0 + e1);
                C[(size_t)gr * 2 + 0] = e0 * si;
                C[(size_t)gr * 2 + 1] = e1 * si;
            }
        }
    } else {
        // bias + mask + lrelu, stage to smem for coalesced write
#pragma unroll
        for (int mf = 0; mf < 2; ++mf) {
            int r0loc = wm * 32 + mf * 16 + g;
            int gr0 = rowBase + r0loc;
            int gr1 = gr0 + 8;
            float m0 = (gr0 < M && __ldg(inv0 + gr0) > 0.f) ? 1.f : 0.f;
            float m1 = (gr1 < M && __ldg(inv0 + gr1) > 0.f) ? 1.f : 0.f;
#pragma unroll
            for (int nf = 0; nf < 8; ++nf) {
                int col = wn * 64 + nf * 8 + t * 2;
                float bva = __ldg(bias0 + col);
                float bvb = __ldg(bias0 + col + 1);
                const float* c = acc[mf][nf];
                float v0 = c[0] + m0 * bva;
                float v1 = c[1] + m0 * bvb;
                float v2 = c[2] + m1 * bva;
                float v3 = c[3] + m1 * bvb;
                if (LRELU) {
                    v0 = v0 > 0.f ? v0 : 0.01f * v0;
                    v1 = v1 > 0.f ? v1 : 0.01f * v1;
                    v2 = v2 > 0.f ? v2 : 0.01f * v2;
                    v3 = v3 > 0.f ? v3 : 0.01f * v3;
                }
                stage[r0loc * 132 + col]       = v0;
                stage[r0loc * 132 + col + 1]   = v1;
                stage[(r0loc + 8) * 132 + col]     = v2;
                stage[(r0loc + 8) * 132 + col + 1] = v3;
            }
        }
        __syncthreads();
#pragma unroll 4
        for (int it = 0; it < 16; ++it) {
            int row = it * 8 + (tid >> 5);
            int c4  = (tid & 31) * 4;
            int gr  = rowBase + row;
            if (gr < M) {
                float4 v = *reinterpret_cast<const float4*>(stage + row * 132 + c4);
                *reinterpret_cast<float4*>(C + (size_t)gr * 128 + c4) = v;
            }
        }
    }
}

// ---------------------------------------------------------------------------
// Host launcher
// ---------------------------------------------------------------------------
static const int SMEM_TILES = 4 * 128 * AS * 2;              // 24576 B
static const int SMEM_L1    = SMEM_TILES + 128 * 132 * 4;    // 92160 B
static const int SMEM_FIN   = SMEM_TILES + 256 * 4;          // 25600 B

extern "C" void kernel_launch(void* const* d_in, const int* in_sizes, int n_in,
                              void* d_out, int out_size)
{
    const float* x_target = (const float*)d_in[0];
    const float* w1    = (const float*)d_in[3];
    const float* b1    = (const float*)d_in[4];
    const float* w2    = (const float*)d_in[5];
    const float* b2    = (const float*)d_in[6];
    const float* w_out = (const float*)d_in[7];
    const float* b_out = (const float*)d_in[8];
    const int* src0 = (const int*)d_in[9];
    const int* dst0 = (const int*)d_in[10];
    const int* src1 = (const int*)d_in[11];
    const int* dst1 = (const int*)d_in[12];
    const int* src2 = (const int*)d_in[13];
    const int* dst2 = (const int*)d_in[14];
    const int* src3 = (const int*)d_in[15];
    const int* dst3 = (const int*)d_in[16];
    const int E0 = in_sizes[9];
    const int E1 = in_sizes[11];
    const int E2 = in_sizes[13];
    const int E3 = in_sizes[15];

    float *agg0, *agg1, *agg2, *agg3, *h1c, *h1i;
    float *inv0, *inv1, *inv2, *inv3;
    int *deg0, *deg1, *deg2, *deg3;
    __nv_bfloat16 *wthi, *wtlo;
    cudaGetSymbolAddress((void**)&agg0, g_agg0);
    cudaGetSymbolAddress((void**)&agg1, g_agg1);
    cudaGetSymbolAddress((void**)&agg2, g_agg2);
    cudaGetSymbolAddress((void**)&agg3, g_agg3);
    cudaGetSymbolAddress((void**)&h1c,  g_h1c);
    cudaGetSymbolAddress((void**)&h1i,  g_h1i);
    cudaGetSymbolAddress((void**)&deg0, g_deg0);
    cudaGetSymbolAddress((void**)&deg1, g_deg1);
    cudaGetSymbolAddress((void**)&deg2, g_deg2);
    cudaGetSymbolAddress((void**)&deg3, g_deg3);
    cudaGetSymbolAddress((void**)&inv0, g_inv0);
    cudaGetSymbolAddress((void**)&inv1, g_inv1);
    cudaGetSymbolAddress((void**)&inv2, g_inv2);
    cudaGetSymbolAddress((void**)&inv3, g_inv3);
    cudaGetSymbolAddress((void**)&wthi, g_wthi);
    cudaGetSymbolAddress((void**)&wtlo, g_wtlo);

    // allow >48KB dynamic smem on the layer-1 GEMM (idempotent)
    cudaFuncSetAttribute(gemm_tc<1, true, false>,
                         cudaFuncAttributeMaxDynamicSharedMemorySize, SMEM_L1);

    // Zero accumulators
    cudaMemsetAsync(agg0, 0, (size_t)NT * 128 * sizeof(float));
    cudaMemsetAsync(agg2, 0, (size_t)NT * 128 * sizeof(float));
    cudaMemsetAsync(agg1, 0, (size_t)NC * 128 * sizeof(float));
    cudaMemsetAsync(agg3, 0, (size_t)NI * 128 * sizeof(float));
    cudaMemsetAsync(deg0, 0, (size_t)NT * sizeof(int));
    cudaMemsetAsync(deg2, 0, (size_t)NT * sizeof(int));
    cudaMemsetAsync(deg1, 0, (size_t)NC * sizeof(int));
    cudaMemsetAsync(deg3, 0, (size_t)NI * sizeof(int));

    // Weight prep (transpose + hi/lo split)
    wprep_kernel<<<(4 * 16384 + 255) / 256, 256>>>(w1, w2);

    // ---- Layer 1 (only dst types card & ip are live) ----
    agg_kernel<<<(E1 + 7) / 8, 256>>>(x_target, src1, dst1, agg1, deg1, E1);
    agg_kernel<<<(E3 + 7) / 8, 256>>>(x_target, src3, dst3, agg3, deg3, E3);
    inv_kernel<<<(NC + 255) / 256, 256>>>(deg1, inv1, NC);
    inv_kernel<<<(NI + 255) / 256, 256>>>(deg3, inv3, NI);

    gemm_tc<1, true, false><<<(NC + 127) / 128, 256, SMEM_L1>>>(
        agg1, inv1, nullptr, nullptr,
        wthi + 0 * 16384, wtlo + 0 * 16384, nullptr, nullptr,
        b1 + 128, nullptr, nullptr, nullptr, h1c, NC);
    gemm_tc<1, true, false><<<(NI + 127) / 128, 256, SMEM_L1>>>(
        agg3, inv3, nullptr, nullptr,
        wthi + 1 * 16384, wtlo + 1 * 16384, nullptr, nullptr,
        b1 + 384, nullptr, nullptr, nullptr, h1i, NI);

    // ---- Layer 2 (only dst type target is live) ----
    agg_kernel<<<(E0 + 7) / 8, 256>>>(h1c, src0, dst0, agg0, deg0, E0);
    agg_kernel<<<(E2 + 7) / 8, 256>>>(h1i, src2, dst2, agg2, deg2, E2);
    inv_kernel<<<(NT + 255) / 256, 256>>>(deg0, inv0, NT);
    inv_kernel<<<(NT + 255) / 256, 256>>>(deg2, inv2, NT);

    gemm_tc<2, false, true><<<(NT + 127) / 128, 256, SMEM_FIN>>>(
        agg0, inv0, agg2, inv2,
        wthi + 2 * 16384, wtlo + 2 * 16384, wthi + 3 * 16384, wtlo + 3 * 16384,
        b2 + 0, b2 + 256, w_out, b_out, (float*)d_out, NT);
}